// round 1
// baseline (speedup 1.0000x reference)
#include <cuda_runtime.h>

// Problem constants
#define NB 16384
#define ND 5000
#define NL 64
#define NJ 192            // 3*L stacked features
#define DEC_SCALE 0.0159f

// Device-global scratch (no cudaMalloc allowed)
__device__ float g_H[NB * NJ];          // [B, 192] stacked hidden
__device__ float g_Wenc[NJ * ND];       // [192, 5000] stacked encoder rows
__device__ float g_Wdec[NJ * ND];       // [192, 5000] stacked decoder rows

// ---------------------------------------------------------------------------
// Pack the 3 encoder weights into g_Wenc[j][d] and the 3 decoder weights
// into g_Wdec[j][d] so both big GEMMs are uniform.
//   enc rows: [W_base(64,5000); W_enc_batch; W_enc_cell]
//   dec rows: [W_base(64,5000); W_dec_batch.T; W_dec_cell.T]  (Wdec is [5000,64])
// ---------------------------------------------------------------------------
__global__ void pack_kernel(const float* __restrict__ Wb,
                            const float* __restrict__ Web,
                            const float* __restrict__ Wdb,
                            const float* __restrict__ Wec,
                            const float* __restrict__ Wdc) {
    int idx = blockIdx.x * blockDim.x + threadIdx.x;
    if (idx >= NJ * ND) return;
    int j = idx / ND;
    int d = idx - j * ND;
    float e, w;
    if (j < 64) {
        e = Wb[j * ND + d];
        w = Wb[j * ND + d];
    } else if (j < 128) {
        e = Web[(j - 64) * ND + d];
        w = Wdb[d * 64 + (j - 64)];
    } else {
        e = Wec[(j - 128) * ND + d];
        w = Wdc[d * 64 + (j - 128)];
    }
    g_Wenc[idx] = e;
    g_Wdec[idx] = w;
}

// ---------------------------------------------------------------------------
// Encode GEMM: g_H[B,192] = expr[B,5000] @ g_Wenc^T
// Block tile 64(M) x 192(N), BK=32, 256 threads, per-thread 4x12 micro-tile.
// ---------------------------------------------------------------------------
__global__ __launch_bounds__(256) void encode_kernel(const float* __restrict__ A) {
    __shared__ float As[64][33];
    __shared__ float Bs[192][33];

    const int tx = threadIdx.x & 15;   // 16 col groups
    const int ty = threadIdx.x >> 4;   // 16 row groups
    const int row0 = blockIdx.x * 64;

    float acc[4][12];
#pragma unroll
    for (int i = 0; i < 4; i++)
#pragma unroll
        for (int j = 0; j < 12; j++) acc[i][j] = 0.f;

    for (int kt = 0; kt < (ND + 31) / 32; kt++) {
        const int k0 = kt * 32;
        // A tile: 64x32 (8 elems/thread), coalesced in k
#pragma unroll
        for (int i = 0; i < 8; i++) {
            int e = threadIdx.x + i * 256;
            int r = e >> 5, k = e & 31;
            int kg = k0 + k;
            As[r][k] = (kg < ND) ? A[(size_t)(row0 + r) * ND + kg] : 0.f;
        }
        // B tile: 192x32 (24 elems/thread), coalesced in k
#pragma unroll
        for (int i = 0; i < 24; i++) {
            int e = threadIdx.x + i * 256;
            int n = e >> 5, k = e & 31;
            int kg = k0 + k;
            Bs[n][k] = (kg < ND) ? g_Wenc[(size_t)n * ND + kg] : 0.f;
        }
        __syncthreads();

#pragma unroll
        for (int k = 0; k < 32; k++) {
            float a[4], b[12];
#pragma unroll
            for (int i = 0; i < 4; i++) a[i] = As[ty + i * 16][k];
#pragma unroll
            for (int j = 0; j < 12; j++) b[j] = Bs[tx + j * 16][k];
#pragma unroll
            for (int i = 0; i < 4; i++)
#pragma unroll
                for (int j = 0; j < 12; j++) acc[i][j] = fmaf(a[i], b[j], acc[i][j]);
        }
        __syncthreads();
    }

#pragma unroll
    for (int i = 0; i < 4; i++)
#pragma unroll
        for (int j = 0; j < 12; j++)
            g_H[(size_t)(row0 + ty + i * 16) * NJ + tx + j * 16] = acc[i][j];
}

// ---------------------------------------------------------------------------
// Heads: per-row double 64x64 matvec with gathered weights, both modalities.
// One warp per row; lane m holds outputs m and m+32; x broadcast via shfl.
// Folds DEC_SCALE into the stored result.
// ---------------------------------------------------------------------------
__device__ __forceinline__ void apply_heads_row(float* __restrict__ h,
                                                const float* __restrict__ Ws,
                                                const float* __restrict__ Wt,
                                                int lane) {
    float x0 = h[lane];
    float x1 = h[lane + 32];
    float y0 = 0.f, y1 = 0.f;
#pragma unroll
    for (int l = 0; l < 64; l++) {
        float xv = (l < 32) ? __shfl_sync(0xffffffffu, x0, l)
                            : __shfl_sync(0xffffffffu, x1, l - 32);
        y0 = fmaf(Ws[lane * 64 + l], xv, y0);
        y1 = fmaf(Ws[(lane + 32) * 64 + l], xv, y1);
    }
    float z0 = 0.f, z1 = 0.f;
#pragma unroll
    for (int l = 0; l < 64; l++) {
        float yv = (l < 32) ? __shfl_sync(0xffffffffu, y0, l)
                            : __shfl_sync(0xffffffffu, y1, l - 32);
        z0 = fmaf(Wt[lane * 64 + l], yv, z0);
        z1 = fmaf(Wt[(lane + 32) * 64 + l], yv, z1);
    }
    h[lane] = z0 * DEC_SCALE;
    h[lane + 32] = z1 * DEC_SCALE;
}

__global__ __launch_bounds__(256) void heads_kernel(const int* __restrict__ sb,
                                                    const int* __restrict__ tb,
                                                    const int* __restrict__ sc,
                                                    const int* __restrict__ tc,
                                                    const float* __restrict__ Whb,
                                                    const float* __restrict__ Whc) {
    int row = blockIdx.x * 8 + (threadIdx.x >> 5);
    if (row >= NB) return;
    int lane = threadIdx.x & 31;
    float* Hrow = g_H + (size_t)row * NJ;
    apply_heads_row(Hrow + 64,  Whb + (size_t)sb[row] * 4096, Whb + (size_t)tb[row] * 4096, lane);
    apply_heads_row(Hrow + 128, Whc + (size_t)sc[row] * 4096, Whc + (size_t)tc[row] * 4096, lane);
}

// ---------------------------------------------------------------------------
// Decode GEMM: out[B,5000] = g_H[B,192] @ g_Wdec[192,5000]
// Block tile 64(M) x 128(N), BK=32 (K=192 -> 6 tiles), 256 threads, 4x8 micro.
// ---------------------------------------------------------------------------
__global__ __launch_bounds__(256) void decode_kernel(float* __restrict__ out) {
    __shared__ float As[64][33];
    __shared__ float Bs[32][132];

    const int tx = threadIdx.x & 15;
    const int ty = threadIdx.x >> 4;
    const int row0 = blockIdx.y * 64;
    const int col0 = blockIdx.x * 128;

    float acc[4][8];
#pragma unroll
    for (int i = 0; i < 4; i++)
#pragma unroll
        for (int j = 0; j < 8; j++) acc[i][j] = 0.f;

    for (int kt = 0; kt < 6; kt++) {
        const int k0 = kt * 32;
        // A tile 64x32: 8 elems/thread
#pragma unroll
        for (int i = 0; i < 8; i++) {
            int e = threadIdx.x + i * 256;
            int r = e >> 5, k = e & 31;
            As[r][k] = g_H[(size_t)(row0 + r) * NJ + k0 + k];
        }
        // B tile 32x128: 16 elems/thread, coalesced in n
#pragma unroll
        for (int i = 0; i < 16; i++) {
            int e = threadIdx.x + i * 256;
            int k = e >> 7, n = e & 127;
            int ng = col0 + n;
            Bs[k][n] = (ng < ND) ? g_Wdec[(size_t)(k0 + k) * ND + ng] : 0.f;
        }
        __syncthreads();

#pragma unroll
        for (int k = 0; k < 32; k++) {
            float a[4], b[8];
#pragma unroll
            for (int i = 0; i < 4; i++) a[i] = As[ty + i * 16][k];
#pragma unroll
            for (int j = 0; j < 8; j++) b[j] = Bs[k][tx + j * 16];
#pragma unroll
            for (int i = 0; i < 4; i++)
#pragma unroll
                for (int j = 0; j < 8; j++) acc[i][j] = fmaf(a[i], b[j], acc[i][j]);
        }
        __syncthreads();
    }

#pragma unroll
    for (int i = 0; i < 4; i++) {
        int rg = row0 + ty + i * 16;
#pragma unroll
        for (int j = 0; j < 8; j++) {
            int ng = col0 + tx + j * 16;
            if (ng < ND) out[(size_t)rg * ND + ng] = acc[i][j];
        }
    }
}

// ---------------------------------------------------------------------------
// kernel_launch — inputs per metadata order:
// 0 expr[B,D] f32 | 1 src_batch | 2 tgt_batch | 3 src_cell | 4 tgt_cell (i32)
// 5 W_base[64,5000] | 6 W_enc_batch[64,5000] | 7 W_dec_batch[5000,64]
// 8 W_heads_batch[24,64,64] | 9 W_enc_cell[64,5000] | 10 W_dec_cell[5000,64]
// 11 W_heads_cell[10,64,64]
// ---------------------------------------------------------------------------
extern "C" void kernel_launch(void* const* d_in, const int* in_sizes, int n_in,
                              void* d_out, int out_size) {
    const float* expr = (const float*)d_in[0];
    const int* sb = (const int*)d_in[1];
    const int* tb = (const int*)d_in[2];
    const int* sc = (const int*)d_in[3];
    const int* tc = (const int*)d_in[4];
    const float* Wb  = (const float*)d_in[5];
    const float* Web = (const float*)d_in[6];
    const float* Wdb = (const float*)d_in[7];
    const float* Whb = (const float*)d_in[8];
    const float* Wec = (const float*)d_in[9];
    const float* Wdc = (const float*)d_in[10];
    const float* Whc = (const float*)d_in[11];
    float* out = (float*)d_out;

    pack_kernel<<<(NJ * ND + 255) / 256, 256>>>(Wb, Web, Wdb, Wec, Wdc);
    encode_kernel<<<NB / 64, 256>>>(expr);
    heads_kernel<<<NB / 8, 256>>>(sb, tb, sc, tc, Whb, Whc);
    decode_kernel<<<dim3((ND + 127) / 128, NB / 64), 256>>>(out);
}

// round 3
// speedup vs baseline: 3.5000x; 3.5000x over previous
#include <cuda_runtime.h>
#include <cuda_bf16.h>
#include <cstdint>

#define NB 16384
#define ND 5000
#define NJ 192
#define KENC_PAD 5056          // 158 * 32
#define NDEC_PAD 5120          // 40 * 128
#define DEC_SCALE 0.0159f
#define CARD_B 24
#define CARD_C 10

// ---------------- device-global scratch (no cudaMalloc allowed) -------------
__device__ __align__(16) float         g_H[NB * NJ];            // fp32 hidden
__device__ __align__(16) __nv_bfloat16 g_Hhi[NB * NJ];
__device__ __align__(16) __nv_bfloat16 g_Hlo[NB * NJ];
__device__ __align__(16) __nv_bfloat16 g_WencHi[NJ * KENC_PAD]; // [n=192][k]
__device__ __align__(16) __nv_bfloat16 g_WencLo[NJ * KENC_PAD];
__device__ __align__(16) __nv_bfloat16 g_WdTHi[NDEC_PAD * NJ];  // [n][k=192]
__device__ __align__(16) __nv_bfloat16 g_WdTLo[NDEC_PAD * NJ];
__device__ __align__(16) float         g_Mb[CARD_B * CARD_B * 4096];
__device__ __align__(16) float         g_Mc[CARD_C * CARD_C * 4096];

// ---------------- mma.sync helpers (generic PTX, works on compute_103) -------
__device__ __forceinline__ void ldsm4(uint32_t* r, const void* p) {
    uint32_t a = (uint32_t)__cvta_generic_to_shared(p);
    asm volatile("ldmatrix.sync.aligned.m8n8.x4.shared.b16 {%0,%1,%2,%3}, [%4];"
                 : "=r"(r[0]), "=r"(r[1]), "=r"(r[2]), "=r"(r[3]) : "r"(a));
}
__device__ __forceinline__ void ldsm2(uint32_t* r, const void* p) {
    uint32_t a = (uint32_t)__cvta_generic_to_shared(p);
    asm volatile("ldmatrix.sync.aligned.m8n8.x2.shared.b16 {%0,%1}, [%2];"
                 : "=r"(r[0]), "=r"(r[1]) : "r"(a));
}
__device__ __forceinline__ void mma16816(float* c, const uint32_t* a, const uint32_t* b) {
    asm volatile("mma.sync.aligned.m16n8k16.row.col.f32.bf16.bf16.f32 "
                 "{%0,%1,%2,%3},{%4,%5,%6,%7},{%8,%9},{%0,%1,%2,%3};"
                 : "+f"(c[0]), "+f"(c[1]), "+f"(c[2]), "+f"(c[3])
                 : "r"(a[0]), "r"(a[1]), "r"(a[2]), "r"(a[3]), "r"(b[0]), "r"(b[1]));
}
// fp32 -> (hi,lo) bf16x2 packed
__device__ __forceinline__ void split2(float f0, float f1, uint32_t& h, uint32_t& l) {
    __nv_bfloat16 h0 = __float2bfloat16_rn(f0);
    __nv_bfloat16 h1 = __float2bfloat16_rn(f1);
    __nv_bfloat16 l0 = __float2bfloat16_rn(f0 - __bfloat162float(h0));
    __nv_bfloat16 l1 = __float2bfloat16_rn(f1 - __bfloat162float(h1));
    h = (uint32_t)__bfloat16_as_ushort(h0) | ((uint32_t)__bfloat16_as_ushort(h1) << 16);
    l = (uint32_t)__bfloat16_as_ushort(l0) | ((uint32_t)__bfloat16_as_ushort(l1) << 16);
}

// ---------------- pack kernels ----------------------------------------------
__global__ void pack_enc_kernel(const float* __restrict__ Wb,
                                const float* __restrict__ Web,
                                const float* __restrict__ Wec) {
    int idx = blockIdx.x * blockDim.x + threadIdx.x;   // 192*KENC_PAD
    int j = idx / KENC_PAD, d = idx - j * KENC_PAD;
    float v = 0.f;
    if (d < ND) {
        if (j < 64)       v = Wb[j * ND + d];
        else if (j < 128) v = Web[(j - 64) * ND + d];
        else              v = Wec[(j - 128) * ND + d];
    }
    __nv_bfloat16 h = __float2bfloat16_rn(v);
    g_WencHi[idx] = h;
    g_WencLo[idx] = __float2bfloat16_rn(v - __bfloat162float(h));
}
__global__ void pack_dec_kernel(const float* __restrict__ Wb,
                                const float* __restrict__ Wdb,
                                const float* __restrict__ Wdc) {
    int idx = blockIdx.x * blockDim.x + threadIdx.x;   // NDEC_PAD*192
    int n = idx / NJ, j = idx - n * NJ;
    float v = 0.f;
    if (n < ND) {
        if (j < 64)       v = Wb[j * ND + n];
        else if (j < 128) v = Wdb[n * 64 + (j - 64)];
        else              v = Wdc[n * 64 + (j - 128)];
    }
    __nv_bfloat16 h = __float2bfloat16_rn(v);
    g_WdTHi[idx] = h;
    g_WdTLo[idx] = __float2bfloat16_rn(v - __bfloat162float(h));
}

// ---------------- composite: M[t,s] = W[t] @ W[s] (64x64x64 per block) -------
__global__ __launch_bounds__(256) void composite_kernel(const float* __restrict__ Whb,
                                                        const float* __restrict__ Whc) {
    __shared__ float sT[4096], sS[4096];
    int pair = blockIdx.x;
    const float *Wt, *Ws;
    float* out;
    if (pair < CARD_B * CARD_B) {
        Wt = Whb + (size_t)(pair / CARD_B) * 4096;
        Ws = Whb + (size_t)(pair % CARD_B) * 4096;
        out = g_Mb + (size_t)pair * 4096;
    } else {
        int p = pair - CARD_B * CARD_B;
        Wt = Whc + (size_t)(p / CARD_C) * 4096;
        Ws = Whc + (size_t)(p % CARD_C) * 4096;
        out = g_Mc + (size_t)p * 4096;
    }
    int tid = threadIdx.x;
    for (int i = tid; i < 4096; i += 256) { sT[i] = Wt[i]; sS[i] = Ws[i]; }
    __syncthreads();
    int m = tid >> 2, n0 = (tid & 3) * 16;
    float c[16];
#pragma unroll
    for (int j = 0; j < 16; j++) c[j] = 0.f;
    for (int l = 0; l < 64; l++) {
        float a = sT[m * 64 + l];
#pragma unroll
        for (int j = 0; j < 16; j++) c[j] = fmaf(a, sS[l * 64 + n0 + j], c[j]);
    }
#pragma unroll
    for (int j = 0; j < 16; j++) out[m * 64 + n0 + j] = c[j];
}

// ---------------- encode: g_H[B,192] = expr @ Wenc^T  (HMMA split bf16) ------
// Block 128(M) x 192(N), 8 warps (4M x 2N), warp tile 32x96, BK=32, NT=158.
#define ENC_SMEM_BYTES (2 * (128 * 40 + 192 * 40) * 2)   // 51200
__global__ __launch_bounds__(256, 1) void encode_kernel(const float* __restrict__ A) {
    extern __shared__ __nv_bfloat16 sm[];
    __nv_bfloat16* sAhi = sm;                 // [128][40]
    __nv_bfloat16* sAlo = sAhi + 128 * 40;
    __nv_bfloat16* sBhi = sAlo + 128 * 40;    // [192][40]
    __nv_bfloat16* sBlo = sBhi + 192 * 40;

    const int tid = threadIdx.x, wid = tid >> 5, lane = tid & 31;
    const int row0 = blockIdx.x * 128;
    const int wm = (wid & 3) * 32, wn = (wid >> 2) * 96;

    float acc[2][12][4];
#pragma unroll
    for (int i = 0; i < 2; i++)
#pragma unroll
        for (int j = 0; j < 12; j++)
#pragma unroll
            for (int k = 0; k < 4; k++) acc[i][j][k] = 0.f;

    float4 av[2][2];
    uint4 bvh[3], bvl[3];

    auto load_regs = [&](int kt) {
        const int k0 = kt * 32;
#pragma unroll
        for (int u = 0; u < 2; u++) {
            int unit = tid + u * 256;              // 512 A units
            int r = unit >> 2, c = unit & 3;
            int kg = k0 + c * 8;
            if (kg < ND) {
                const float4* p = (const float4*)(A + (size_t)(row0 + r) * ND + kg);
                av[u][0] = p[0]; av[u][1] = p[1];
            } else {
                av[u][0] = make_float4(0.f, 0.f, 0.f, 0.f);
                av[u][1] = av[u][0];
            }
        }
#pragma unroll
        for (int u = 0; u < 3; u++) {
            int unit = tid + u * 256;              // 768 B units
            int n = unit >> 2, c = unit & 3;
            size_t off = (size_t)n * KENC_PAD + k0 + c * 8;
            bvh[u] = *(const uint4*)(g_WencHi + off);
            bvl[u] = *(const uint4*)(g_WencLo + off);
        }
    };
    auto store_smem = [&]() {
#pragma unroll
        for (int u = 0; u < 2; u++) {
            int unit = tid + u * 256;
            int r = unit >> 2, c = unit & 3;
            uint32_t h[4], l[4];
            split2(av[u][0].x, av[u][0].y, h[0], l[0]);
            split2(av[u][0].z, av[u][0].w, h[1], l[1]);
            split2(av[u][1].x, av[u][1].y, h[2], l[2]);
            split2(av[u][1].z, av[u][1].w, h[3], l[3]);
            int o = r * 40 + c * 8;
            *(uint4*)(sAhi + o) = make_uint4(h[0], h[1], h[2], h[3]);
            *(uint4*)(sAlo + o) = make_uint4(l[0], l[1], l[2], l[3]);
        }
#pragma unroll
        for (int u = 0; u < 3; u++) {
            int unit = tid + u * 256;
            int n = unit >> 2, c = unit & 3;
            int o = n * 40 + c * 8;
            *(uint4*)(sBhi + o) = bvh[u];
            *(uint4*)(sBlo + o) = bvl[u];
        }
    };

    const int NT = KENC_PAD / 32;   // 158
    load_regs(0);
    for (int kt = 0; kt < NT; kt++) {
        __syncthreads();
        store_smem();
        __syncthreads();
        if (kt + 1 < NT) load_regs(kt + 1);

#pragma unroll
        for (int ks = 0; ks < 2; ks++) {
            const int kk = ks * 16;
            uint32_t ahi[2][4], alo[2][4];
#pragma unroll
            for (int mt = 0; mt < 2; mt++) {
                int o = (wm + mt * 16 + (lane & 15)) * 40 + kk + (lane >> 4) * 8;
                ldsm4(ahi[mt], sAhi + o);
                ldsm4(alo[mt], sAlo + o);
            }
            uint32_t bhi[12][2], blo[12][2];
#pragma unroll
            for (int nt = 0; nt < 12; nt++) {
                int o = (wn + nt * 8 + (lane & 7)) * 40 + kk + ((lane >> 3) & 1) * 8;
                ldsm2(bhi[nt], sBhi + o);
                ldsm2(blo[nt], sBlo + o);
            }
#pragma unroll
            for (int mt = 0; mt < 2; mt++)
#pragma unroll
                for (int nt = 0; nt < 12; nt++) {
                    mma16816(acc[mt][nt], ahi[mt], bhi[nt]);
                    mma16816(acc[mt][nt], ahi[mt], blo[nt]);
                    mma16816(acc[mt][nt], alo[mt], bhi[nt]);
                }
        }
    }

    // epilogue -> g_H fp32
#pragma unroll
    for (int mt = 0; mt < 2; mt++) {
        int r = row0 + wm + mt * 16 + (lane >> 2);
#pragma unroll
        for (int nt = 0; nt < 12; nt++) {
            int cgl = wn + nt * 8 + (lane & 3) * 2;
            *(float2*)(g_H + (size_t)r * NJ + cgl) =
                make_float2(acc[mt][nt][0], acc[mt][nt][1]);
            *(float2*)(g_H + (size_t)(r + 8) * NJ + cgl) =
                make_float2(acc[mt][nt][2], acc[mt][nt][3]);
        }
    }
}

// ---------------- heads: per-row composite matvec, coalesced + shfl-reduce ---
__device__ __forceinline__ void store_split(size_t i, float v) {
    __nv_bfloat16 h = __float2bfloat16_rn(v);
    g_Hhi[i] = h;
    g_Hlo[i] = __float2bfloat16_rn(v - __bfloat162float(h));
}
__device__ __forceinline__ void matvec64(const float* __restrict__ M,
                                         float2 x, int lane, float& z0, float& z1) {
#pragma unroll 8
    for (int m = 0; m < 64; m++) {
        float2 w = ((const float2*)(M + m * 64))[lane];
        float s = w.x * x.x + w.y * x.y;
        s += __shfl_xor_sync(0xffffffffu, s, 16);
        s += __shfl_xor_sync(0xffffffffu, s, 8);
        s += __shfl_xor_sync(0xffffffffu, s, 4);
        s += __shfl_xor_sync(0xffffffffu, s, 2);
        s += __shfl_xor_sync(0xffffffffu, s, 1);
        if ((m & 31) == lane) { if (m < 32) z0 = s; else z1 = s; }
    }
}
__global__ __launch_bounds__(256) void heads_kernel(const int* __restrict__ sb_,
                                                    const int* __restrict__ tb_,
                                                    const int* __restrict__ sc_,
                                                    const int* __restrict__ tc_) {
    int row = blockIdx.x * 8 + (threadIdx.x >> 5);
    int lane = threadIdx.x & 31;
    const float* Hrow = g_H + (size_t)row * NJ;
    float2 xb = ((const float2*)(Hrow + 64))[lane];
    float2 xc = ((const float2*)(Hrow + 128))[lane];
    const float* Mb = g_Mb + (size_t)(tb_[row] * CARD_B + sb_[row]) * 4096;
    const float* Mc = g_Mc + (size_t)(tc_[row] * CARD_C + sc_[row]) * 4096;
    float zb0 = 0.f, zb1 = 0.f, zc0 = 0.f, zc1 = 0.f;
    matvec64(Mb, xb, lane, zb0, zb1);
    matvec64(Mc, xc, lane, zc0, zc1);
    float b0 = Hrow[lane], b1 = Hrow[lane + 32];
    size_t o = (size_t)row * NJ;
    store_split(o + lane,        b0);
    store_split(o + lane + 32,   b1);
    store_split(o + 64 + lane,   zb0 * DEC_SCALE);
    store_split(o + 96 + lane,   zb1 * DEC_SCALE);
    store_split(o + 128 + lane,  zc0 * DEC_SCALE);
    store_split(o + 160 + lane,  zc1 * DEC_SCALE);
}

// ---------------- decode: out[B,5000] = Hsplit @ WdT^T (HMMA split bf16) -----
// Block 128(M) x 128(N), 8 warps (4M x 2N), warp tile 32x64, BK=32, NT=6.
__global__ __launch_bounds__(256, 1) void decode_kernel(float* __restrict__ out) {
    __shared__ __nv_bfloat16 sAhi[128 * 40], sAlo[128 * 40];
    __shared__ __nv_bfloat16 sBhi[128 * 40], sBlo[128 * 40];

    const int tid = threadIdx.x, wid = tid >> 5, lane = tid & 31;
    const int row0 = blockIdx.y * 128;
    const int col0 = blockIdx.x * 128;
    const int wm = (wid & 3) * 32, wn = (wid >> 2) * 64;

    float acc[2][8][4];
#pragma unroll
    for (int i = 0; i < 2; i++)
#pragma unroll
        for (int j = 0; j < 8; j++)
#pragma unroll
            for (int k = 0; k < 4; k++) acc[i][j][k] = 0.f;

    uint4 avh[2], avl[2], bvh[2], bvl[2];
    auto load_regs = [&](int kt) {
        const int k0 = kt * 32;
#pragma unroll
        for (int u = 0; u < 2; u++) {
            int unit = tid + u * 256;
            int r = unit >> 2, c = unit & 3;
            size_t oa = (size_t)(row0 + r) * NJ + k0 + c * 8;
            avh[u] = *(const uint4*)(g_Hhi + oa);
            avl[u] = *(const uint4*)(g_Hlo + oa);
            size_t ob = (size_t)(col0 + r) * NJ + k0 + c * 8;
            bvh[u] = *(const uint4*)(g_WdTHi + ob);
            bvl[u] = *(const uint4*)(g_WdTLo + ob);
        }
    };
    auto store_smem = [&]() {
#pragma unroll
        for (int u = 0; u < 2; u++) {
            int unit = tid + u * 256;
            int r = unit >> 2, c = unit & 3;
            int o = r * 40 + c * 8;
            *(uint4*)(sAhi + o) = avh[u];
            *(uint4*)(sAlo + o) = avl[u];
            *(uint4*)(sBhi + o) = bvh[u];
            *(uint4*)(sBlo + o) = bvl[u];
        }
    };

    load_regs(0);
#pragma unroll 1
    for (int kt = 0; kt < 6; kt++) {
        __syncthreads();
        store_smem();
        __syncthreads();
        if (kt + 1 < 6) load_regs(kt + 1);

#pragma unroll
        for (int ks = 0; ks < 2; ks++) {
            const int kk = ks * 16;
            uint32_t ahi[2][4], alo[2][4];
#pragma unroll
            for (int mt = 0; mt < 2; mt++) {
                int o = (wm + mt * 16 + (lane & 15)) * 40 + kk + (lane >> 4) * 8;
                ldsm4(ahi[mt], sAhi + o);
                ldsm4(alo[mt], sAlo + o);
            }
            uint32_t bhi[8][2], blo[8][2];
#pragma unroll
            for (int nt = 0; nt < 8; nt++) {
                int o = (wn + nt * 8 + (lane & 7)) * 40 + kk + ((lane >> 3) & 1) * 8;
                ldsm2(bhi[nt], sBhi + o);
                ldsm2(blo[nt], sBlo + o);
            }
#pragma unroll
            for (int mt = 0; mt < 2; mt++)
#pragma unroll
                for (int nt = 0; nt < 8; nt++) {
                    mma16816(acc[mt][nt], ahi[mt], bhi[nt]);
                    mma16816(acc[mt][nt], ahi[mt], blo[nt]);
                    mma16816(acc[mt][nt], alo[mt], bhi[nt]);
                }
        }
    }

#pragma unroll
    for (int mt = 0; mt < 2; mt++) {
        int r = row0 + wm + mt * 16 + (lane >> 2);
#pragma unroll
        for (int nt = 0; nt < 8; nt++) {
            int cg = col0 + wn + nt * 8 + (lane & 3) * 2;
            if (cg < ND) {
                *(float2*)(out + (size_t)r * ND + cg) =
                    make_float2(acc[mt][nt][0], acc[mt][nt][1]);
                *(float2*)(out + (size_t)(r + 8) * ND + cg) =
                    make_float2(acc[mt][nt][2], acc[mt][nt][3]);
            }
        }
    }
}

// ---------------- launch ------------------------------------------------------
extern "C" void kernel_launch(void* const* d_in, const int* in_sizes, int n_in,
                              void* d_out, int out_size) {
    const float* expr = (const float*)d_in[0];
    const int* sb = (const int*)d_in[1];
    const int* tb = (const int*)d_in[2];
    const int* sc = (const int*)d_in[3];
    const int* tc = (const int*)d_in[4];
    const float* Wb  = (const float*)d_in[5];
    const float* Web = (const float*)d_in[6];
    const float* Wdb = (const float*)d_in[7];
    const float* Whb = (const float*)d_in[8];
    const float* Wec = (const float*)d_in[9];
    const float* Wdc = (const float*)d_in[10];
    const float* Whc = (const float*)d_in[11];
    float* out = (float*)d_out;

    cudaFuncSetAttribute(encode_kernel, cudaFuncAttributeMaxDynamicSharedMemorySize,
                         ENC_SMEM_BYTES);

    pack_enc_kernel<<<(NJ * KENC_PAD) / 256, 256>>>(Wb, Web, Wec);
    pack_dec_kernel<<<(NDEC_PAD * NJ) / 256, 256>>>(Wb, Wdb, Wdc);
    composite_kernel<<<CARD_B * CARD_B + CARD_C * CARD_C, 256>>>(Whb, Whc);
    encode_kernel<<<NB / 128, 256, ENC_SMEM_BYTES>>>(expr);
    heads_kernel<<<NB / 8, 256>>>(sb, tb, sc, tc);
    decode_kernel<<<dim3(NDEC_PAD / 128, NB / 128), 256>>>(out);
}